// round 1
// baseline (speedup 1.0000x reference)
#include <cuda_runtime.h>
#include <math.h>
#include <float.h>

#define Bsz 256
#define Ssz 64
#define Tsz 20
#define TD 19            // T-1 decoder steps
#define Hsz 1024
#define Esz 100
#define Vsz 32000
#define TH3 3072         // 3*H
#define EH  1124         // E+H
#define ENC_ROWS (Bsz*Ssz)   // 16384
#define DEC_ROWS (Bsz*TD)    // 4864

// ---------------- scratch (static __device__ — no allocations) ----------------
__device__ float g_embE[ENC_ROWS*Esz];            // 6.5 MB
__device__ float g_gi_e[(size_t)ENC_ROWS*TH3];    // 201 MB  encoder input gates [b*S+s, 3H]
__device__ float g_h[Bsz*Hsz];                    // current hidden
__device__ float g_gh[Bsz*TH3];                   // hidden-side gates for one step
__device__ float g_context[Bsz*Hsz];
__device__ float g_gctx[Bsz*TH3];                 // context @ W_ih_d[:,E:].T + b_ih_d
__device__ float g_embD[DEC_ROWS*Esz];
__device__ float g_gi_d[(size_t)DEC_ROWS*TH3];    // 60 MB   demb @ W_ih_d[:,:E].T, rows b*TD+t
__device__ float g_hall[(size_t)DEC_ROWS*Hsz];    // 20 MB   decoder hiddens, rows t*B+b
__device__ float g_logits[(size_t)DEC_ROWS*Vsz];  // 622 MB
__device__ float g_ce[DEC_ROWS];
__device__ float g_msk[DEC_ROWS];

// ---------------- generic fp32 GEMM: C[m,n] = sum_k A[m,k]*W[n,k] + bias[n] ----
// A: [M,K] lda, W: [N,K] ldw (both K-major => "NT" dot of rows), C: [M,N] ldc.
#define BMT 64
#define BNT 64
#define KT  16
__global__ __launch_bounds__(256) void gemm_nt(
    const float* __restrict__ A, int lda,
    const float* __restrict__ W, int ldw,
    const float* __restrict__ bias,
    float* __restrict__ C, int ldc,
    int M, int N, int K)
{
    __shared__ float As[KT][BMT + 4];
    __shared__ float Ws[KT][BNT + 4];
    const int tid = threadIdx.x;           // 256 threads
    const int bm = blockIdx.y * BMT;
    const int bn = blockIdx.x * BNT;
    const int tx = tid & 15;               // 16 col-groups
    const int ty = tid >> 4;               // 16 row-groups
    const int row0 = ty * 4;
    const int col0 = tx * 4;
    const int lk = tid & 15;               // loader: k within tile
    const int lr = tid >> 4;               // loader: row 0..15 (stride 16)

    float acc[4][4] = {};
    for (int k0 = 0; k0 < K; k0 += KT) {
        const int gk = k0 + lk;
        const bool kok = (gk < K);
#pragma unroll
        for (int i = 0; i < 4; i++) {
            int r = lr + i * 16;
            int gm = bm + r;
            As[lk][r] = (kok && gm < M) ? A[(size_t)gm * lda + gk] : 0.f;
        }
#pragma unroll
        for (int i = 0; i < 4; i++) {
            int r = lr + i * 16;
            int gn = bn + r;
            Ws[lk][r] = (kok && gn < N) ? W[(size_t)gn * ldw + gk] : 0.f;
        }
        __syncthreads();
#pragma unroll
        for (int kk = 0; kk < KT; kk++) {
            float4 av = *reinterpret_cast<const float4*>(&As[kk][row0]);
            float4 wv = *reinterpret_cast<const float4*>(&Ws[kk][col0]);
            float a[4] = {av.x, av.y, av.z, av.w};
            float w[4] = {wv.x, wv.y, wv.z, wv.w};
#pragma unroll
            for (int i = 0; i < 4; i++)
#pragma unroll
                for (int j = 0; j < 4; j++)
                    acc[i][j] += a[i] * w[j];
        }
        __syncthreads();
    }
#pragma unroll
    for (int i = 0; i < 4; i++) {
        int gm = bm + row0 + i;
        if (gm >= M) continue;
#pragma unroll
        for (int j = 0; j < 4; j++) {
            int gn = bn + col0 + j;
            if (gn < N)
                C[(size_t)gm * ldc + gn] = acc[i][j] + (bias ? bias[gn] : 0.f);
        }
    }
}

// ---------------- embeddings ----------------
__global__ void embed_enc(const int* __restrict__ inputs, const float* __restrict__ Eenc) {
    int idx = blockIdx.x * blockDim.x + threadIdx.x;
    if (idx >= ENC_ROWS * Esz) return;
    int row = idx / Esz, e = idx - row * Esz;
    g_embE[idx] = Eenc[(size_t)inputs[row] * Esz + e];
}

__global__ void embed_dec(const int* __restrict__ targets, const float* __restrict__ Edec) {
    int idx = blockIdx.x * blockDim.x + threadIdx.x;
    if (idx >= DEC_ROWS * Esz) return;
    int row = idx / Esz, e = idx - row * Esz;
    int b = row / TD, t = row - b * TD;
    int tok = (t == 0) ? 1 : targets[b * Tsz + t];   // [START, targets[:,1:T-1]]
    g_embD[idx] = Edec[(size_t)tok * Esz + e];
}

// ---------------- hidden init ----------------
__global__ void init_h_enc(const float* __restrict__ h0) {
    int idx = blockIdx.x * blockDim.x + threadIdx.x;
    if (idx < Bsz * Hsz) g_h[idx] = h0[idx];  // h0_enc[0] is contiguous [B,H]
}
__global__ void init_h_dec() {
    int idx = blockIdx.x * blockDim.x + threadIdx.x;
    if (idx < Bsz * Hsz) g_h[idx] = g_context[idx];
}

// ---------------- GRU gate kernels ----------------
__device__ __forceinline__ float sigmoidf(float x) { return 1.f / (1.f + expf(-x)); }

__global__ void enc_gate(const int* __restrict__ lengths, int s) {
    int idx = blockIdx.x * blockDim.x + threadIdx.x;
    if (idx >= Bsz * Hsz) return;
    int b = idx >> 10, j = idx & (Hsz - 1);
    const float* gi = g_gi_e + (size_t)(b * Ssz + s) * TH3;
    const float* gh = g_gh + (size_t)b * TH3;
    float r = sigmoidf(gi[j] + gh[j]);
    float z = sigmoidf(gi[Hsz + j] + gh[Hsz + j]);
    float n = tanhf(gi[2 * Hsz + j] + r * gh[2 * Hsz + j]);
    float hnew = (1.f - z) * n + z * g_h[idx];
    g_h[idx] = hnew;
    if (lengths[b] - 1 == s) g_context[idx] = hnew;
}

__global__ void dec_gate(int t) {
    int idx = blockIdx.x * blockDim.x + threadIdx.x;
    if (idx >= Bsz * Hsz) return;
    int b = idx >> 10, j = idx & (Hsz - 1);
    const float* gi = g_gi_d + (size_t)(b * TD + t) * TH3;
    const float* gc = g_gctx + (size_t)b * TH3;
    const float* gh = g_gh + (size_t)b * TH3;
    float r = sigmoidf(gi[j] + gc[j] + gh[j]);
    float z = sigmoidf(gi[Hsz + j] + gc[Hsz + j] + gh[Hsz + j]);
    float n = tanhf(gi[2 * Hsz + j] + gc[2 * Hsz + j] + r * gh[2 * Hsz + j]);
    float hnew = (1.f - z) * n + z * g_h[idx];
    g_h[idx] = hnew;
    g_hall[(size_t)(t * Bsz + b) * Hsz + j] = hnew;
}

// ---------------- cross entropy over logits rows ----------------
__global__ void ce_kernel(const int* __restrict__ targets) {
    int r = blockIdx.x;                   // r = t*B + b
    int t = r / Bsz, b = r - t * Bsz;
    const float* l = g_logits + (size_t)r * Vsz;
    __shared__ float sdata[256];
    int tid = threadIdx.x;
    float m = -FLT_MAX;
    for (int v = tid; v < Vsz; v += 256) m = fmaxf(m, l[v]);
    sdata[tid] = m; __syncthreads();
    for (int o = 128; o > 0; o >>= 1) {
        if (tid < o) sdata[tid] = fmaxf(sdata[tid], sdata[tid + o]);
        __syncthreads();
    }
    m = sdata[0]; __syncthreads();
    float s = 0.f;
    for (int v = tid; v < Vsz; v += 256) s += expf(l[v] - m);
    sdata[tid] = s; __syncthreads();
    for (int o = 128; o > 0; o >>= 1) {
        if (tid < o) sdata[tid] += sdata[tid + o];
        __syncthreads();
    }
    if (tid == 0) {
        int y = targets[b * Tsz + t + 1];
        g_ce[r] = m + logf(sdata[0]) - l[y];
        g_msk[r] = (y >= 1) ? 1.f : 0.f;
    }
}

__global__ void final_loss_kernel(float* __restrict__ out) {
    __shared__ float s1[256], s2[256];
    __shared__ float total;
    int tid = threadIdx.x;   // 256 == Bsz
    if (tid == 0) total = 0.f;
    __syncthreads();
    for (int t = 0; t < TD; t++) {
        s1[tid] = g_ce[t * Bsz + tid];
        s2[tid] = g_msk[t * Bsz + tid];
        __syncthreads();
        for (int o = 128; o > 0; o >>= 1) {
            if (tid < o) { s1[tid] += s1[tid + o]; s2[tid] += s2[tid + o]; }
            __syncthreads();
        }
        if (tid == 0) total += (s1[0] / Bsz) * (s2[0] / Bsz);
        __syncthreads();
    }
    if (tid == 0) out[0] = total / Tsz;
}

// ---------------- launch ----------------
extern "C" void kernel_launch(void* const* d_in, const int* in_sizes, int n_in,
                              void* d_out, int out_size) {
    const int*   inputs  = (const int*)  d_in[0];
    const int*   targets = (const int*)  d_in[1];
    const int*   lengths = (const int*)  d_in[2];
    const float* h0      = (const float*)d_in[3];
    const float* Eenc    = (const float*)d_in[4];
    const float* Edec    = (const float*)d_in[5];
    const float* Wih_e   = (const float*)d_in[6];   // [3H, E]
    const float* Whh_e   = (const float*)d_in[7];   // [3H, H]
    const float* bih_e   = (const float*)d_in[8];
    const float* bhh_e   = (const float*)d_in[9];
    const float* Wih_d   = (const float*)d_in[10];  // [3H, E+H]
    const float* Whh_d   = (const float*)d_in[11];  // [3H, H]
    const float* bih_d   = (const float*)d_in[12];
    const float* bhh_d   = (const float*)d_in[13];
    const float* Wfc     = (const float*)d_in[14];  // [V, H]
    const float* bfc     = (const float*)d_in[15];
    float* out = (float*)d_out;

    float *p_embE, *p_gi_e, *p_h, *p_gh, *p_ctx, *p_gctx, *p_embD, *p_gi_d, *p_hall, *p_logits;
    cudaGetSymbolAddress((void**)&p_embE,   g_embE);
    cudaGetSymbolAddress((void**)&p_gi_e,   g_gi_e);
    cudaGetSymbolAddress((void**)&p_h,      g_h);
    cudaGetSymbolAddress((void**)&p_gh,     g_gh);
    cudaGetSymbolAddress((void**)&p_ctx,    g_context);
    cudaGetSymbolAddress((void**)&p_gctx,   g_gctx);
    cudaGetSymbolAddress((void**)&p_embD,   g_embD);
    cudaGetSymbolAddress((void**)&p_gi_d,   g_gi_d);
    cudaGetSymbolAddress((void**)&p_hall,   g_hall);
    cudaGetSymbolAddress((void**)&p_logits, g_logits);

    const int EW = Bsz * Hsz;                 // 262144 elementwise work
    dim3 thr(256);

    // --- encoder input gates (batched over all B*S rows) ---
    embed_enc<<<(ENC_ROWS * Esz + 255) / 256, thr>>>(inputs, Eenc);
    gemm_nt<<<dim3(TH3 / BNT, ENC_ROWS / BMT), thr>>>(
        p_embE, Esz, Wih_e, Esz, bih_e, p_gi_e, TH3, ENC_ROWS, TH3, Esz);

    // --- encoder recurrence ---
    init_h_enc<<<(EW + 255) / 256, thr>>>(h0);
    for (int s = 0; s < Ssz; s++) {
        gemm_nt<<<dim3(TH3 / BNT, Bsz / BMT), thr>>>(
            p_h, Hsz, Whh_e, Hsz, bhh_e, p_gh, TH3, Bsz, TH3, Hsz);
        enc_gate<<<(EW + 255) / 256, thr>>>(lengths, s);
    }

    // --- decoder input gates: split context part (step-invariant) from token part ---
    init_h_dec<<<(EW + 255) / 256, thr>>>();
    embed_dec<<<(DEC_ROWS * Esz + 255) / 256, thr>>>(targets, Edec);
    gemm_nt<<<dim3(TH3 / BNT, Bsz / BMT), thr>>>(
        p_ctx, Hsz, Wih_d + Esz, EH, bih_d, p_gctx, TH3, Bsz, TH3, Hsz);
    gemm_nt<<<dim3(TH3 / BNT, DEC_ROWS / BMT), thr>>>(
        p_embD, Esz, Wih_d, EH, nullptr, p_gi_d, TH3, DEC_ROWS, TH3, Esz);

    // --- decoder recurrence (store all hiddens for batched FC) ---
    for (int t = 0; t < TD; t++) {
        gemm_nt<<<dim3(TH3 / BNT, Bsz / BMT), thr>>>(
            p_h, Hsz, Whh_d, Hsz, bhh_d, p_gh, TH3, Bsz, TH3, Hsz);
        dec_gate<<<(EW + 255) / 256, thr>>>(t);
    }

    // --- batched FC + CE + loss ---
    gemm_nt<<<dim3(Vsz / BNT, DEC_ROWS / BMT), thr>>>(
        p_hall, Hsz, Wfc, Hsz, bfc, p_logits, Vsz, DEC_ROWS, Vsz, Hsz);
    ce_kernel<<<DEC_ROWS, thr>>>(targets);
    final_loss_kernel<<<1, thr>>>(out);
}

// round 14
// speedup vs baseline: 2.9950x; 2.9950x over previous
#include <cuda_runtime.h>
#include <cuda_bf16.h>
#include <math.h>
#include <float.h>

typedef __nv_bfloat16 bf16;
typedef unsigned int u32;

#define Bsz 256
#define Ssz 64
#define Tsz 20
#define TD 19            // T-1 decoder steps
#define Hsz 1024
#define Esz 100
#define KPAD 128         // padded K for E-dim GEMMs
#define Vsz 32000
#define TH3 3072         // 3*H
#define EH  1124         // E+H
#define ENC_ROWS (Bsz*Ssz)   // 16384
#define DEC_ROWS (Bsz*TD)    // 4864

// ---------------- scratch (static __device__ — no allocations) ----------------
__device__ float g_gi_e[(size_t)ENC_ROWS*TH3];    // encoder input gates [b*S+s, 3H]
__device__ float g_gi_d[(size_t)DEC_ROWS*TH3];    // decoder token gates [b*TD+t, 3H]
__device__ float g_gh[Bsz*TH3];                   // hidden-side gates (one step)
__device__ float g_gctx[Bsz*TH3];                 // ctx @ W_ih_d[:,E:].T + b_ih_d
__device__ float g_h[Bsz*Hsz];                    // current hidden fp32
__device__ float g_context[Bsz*Hsz];
__device__ float g_logits[(size_t)DEC_ROWS*Vsz];
__device__ float g_ce[DEC_ROWS];
__device__ float g_msk[DEC_ROWS];
// bf16 split activations
__device__ bf16 g_embE_h[(size_t)ENC_ROWS*KPAD], g_embE_l[(size_t)ENC_ROWS*KPAD];
__device__ bf16 g_embD_h[(size_t)DEC_ROWS*KPAD], g_embD_l[(size_t)DEC_ROWS*KPAD];
__device__ bf16 g_h_h[Bsz*Hsz],   g_h_l[Bsz*Hsz];
__device__ bf16 g_ctx_h[Bsz*Hsz], g_ctx_l[Bsz*Hsz];
__device__ bf16 g_hall_h[(size_t)DEC_ROWS*Hsz];   // decoder hiddens (bf16, rows t*B+b)
// bf16 split weights
__device__ bf16 g_Wihe_h[TH3*KPAD],  g_Wihe_l[TH3*KPAD];
__device__ bf16 g_Wihdt_h[TH3*KPAD], g_Wihdt_l[TH3*KPAD];   // token part of W_ih_d
__device__ bf16 g_Wihdc_h[(size_t)TH3*Hsz], g_Wihdc_l[(size_t)TH3*Hsz]; // ctx part
__device__ bf16 g_Whhe_h[(size_t)TH3*Hsz], g_Whhe_l[(size_t)TH3*Hsz];
__device__ bf16 g_Whhd_h[(size_t)TH3*Hsz], g_Whhd_l[(size_t)TH3*Hsz];
__device__ bf16 g_Wfc_h[(size_t)Vsz*Hsz];

// ---------------- mma.sync bf16 GEMM ----------------
// C[m,n] = sum_k A[m,k]*B[n,k] (+bias[n]), fp32 accum.
// NPASS==3: A,B given as (hi,lo) splits; acc = Ah*Bh + Ah*Bl + Al*Bh (near-fp32).
// NPASS==1: plain bf16 (hi only).
// Requires M%64==0, N%64==0, K%32==0, 16B-aligned rows (lda/ldb % 8 == 0).

#define LDMX4(r, addr) \
  asm volatile("ldmatrix.sync.aligned.m8n8.x4.shared.b16 {%0,%1,%2,%3}, [%4];" \
    : "=r"((r)[0]), "=r"((r)[1]), "=r"((r)[2]), "=r"((r)[3]) : "r"(addr))

#define MMA16816(d, a, b0_, b1_) \
  asm volatile("mma.sync.aligned.m16n8k16.row.col.f32.bf16.bf16.f32 " \
    "{%0,%1,%2,%3}, {%4,%5,%6,%7}, {%8,%9}, {%0,%1,%2,%3};" \
    : "+f"((d)[0]), "+f"((d)[1]), "+f"((d)[2]), "+f"((d)[3]) \
    : "r"((a)[0]), "r"((a)[1]), "r"((a)[2]), "r"((a)[3]), "r"(b0_), "r"(b1_))

#define SLD 40   // smem row stride (bf16) — pad 32->40 for conflict-free ldmatrix

template<int NPASS>
__global__ __launch_bounds__(128) void mma_gemm(
    const bf16* __restrict__ Ahi, const bf16* __restrict__ Alo, int lda,
    const bf16* __restrict__ Bhi, const bf16* __restrict__ Blo, int ldb,
    const float* __restrict__ bias, float* __restrict__ C, int ldc,
    int M, int N, int K)
{
    constexpr int NBUF = (NPASS == 3) ? 2 : 1;
    __shared__ __align__(16) bf16 sA[NBUF][64 * SLD];
    __shared__ __align__(16) bf16 sB[NBUF][64 * SLD];

    const int tid  = threadIdx.x;
    const int warp = tid >> 5, lane = tid & 31;
    const int wm = (warp & 1) * 32;       // 2x2 warp grid over 64x64 block
    const int wn = (warp >> 1) * 32;
    const int bm = blockIdx.y * 64, bn = blockIdx.x * 64;

    float acc[2][4][4];
#pragma unroll
    for (int i = 0; i < 2; i++)
#pragma unroll
        for (int j = 0; j < 4; j++)
#pragma unroll
            for (int c = 0; c < 4; c++) acc[i][j][c] = 0.f;

    // ldmatrix per-lane offsets
    const int a_row = lane & 15;                       // + wm + mi*16
    const int a_col = (lane >> 4) * 8;                 // + kk
    const int b_row = (lane & 7) + ((lane >> 4) * 8);  // + wn + nh*16
    const int b_col = ((lane >> 3) & 1) * 8;           // + kk

    const int lrow = tid >> 2;            // loader row (0..31 / +32)
    const int lcol = (tid & 3) << 3;      // loader k-col {0,8,16,24}

    for (int k0 = 0; k0 < K; k0 += 32) {
#pragma unroll
        for (int j = 0; j < 2; j++) {
            int row = lrow + j * 32;
            const size_t ga = (size_t)(bm + row) * lda + k0 + lcol;
            const size_t gb = (size_t)(bn + row) * ldb + k0 + lcol;
            *reinterpret_cast<uint4*>(&sA[0][row * SLD + lcol]) =
                *reinterpret_cast<const uint4*>(Ahi + ga);
            *reinterpret_cast<uint4*>(&sB[0][row * SLD + lcol]) =
                *reinterpret_cast<const uint4*>(Bhi + gb);
            if (NPASS == 3) {
                *reinterpret_cast<uint4*>(&sA[NBUF - 1][row * SLD + lcol]) =
                    *reinterpret_cast<const uint4*>(Alo + ga);
                *reinterpret_cast<uint4*>(&sB[NBUF - 1][row * SLD + lcol]) =
                    *reinterpret_cast<const uint4*>(Blo + gb);
            }
        }
        __syncthreads();

#pragma unroll
        for (int kk = 0; kk < 32; kk += 16) {
            u32 aH[2][4], bH[2][4];
            u32 aL[2][4], bL[2][4];
#pragma unroll
            for (int mi = 0; mi < 2; mi++) {
                u32 ad = (u32)__cvta_generic_to_shared(
                    &sA[0][(wm + mi * 16 + a_row) * SLD + kk + a_col]);
                LDMX4(aH[mi], ad);
                if (NPASS == 3) {
                    u32 ad2 = (u32)__cvta_generic_to_shared(
                        &sA[NBUF - 1][(wm + mi * 16 + a_row) * SLD + kk + a_col]);
                    LDMX4(aL[mi], ad2);
                }
            }
#pragma unroll
            for (int nh = 0; nh < 2; nh++) {
                u32 bd = (u32)__cvta_generic_to_shared(
                    &sB[0][(wn + nh * 16 + b_row) * SLD + kk + b_col]);
                LDMX4(bH[nh], bd);
                if (NPASS == 3) {
                    u32 bd2 = (u32)__cvta_generic_to_shared(
                        &sB[NBUF - 1][(wn + nh * 16 + b_row) * SLD + kk + b_col]);
                    LDMX4(bL[nh], bd2);
                }
            }
#pragma unroll
            for (int mi = 0; mi < 2; mi++)
#pragma unroll
                for (int nf = 0; nf < 4; nf++) {
                    const u32* bh = &bH[nf >> 1][(nf & 1) * 2];
                    MMA16816(acc[mi][nf], aH[mi], bh[0], bh[1]);
                    if (NPASS == 3) {
                        const u32* bl = &bL[nf >> 1][(nf & 1) * 2];
                        MMA16816(acc[mi][nf], aH[mi], bl[0], bl[1]);
                        MMA16816(acc[mi][nf], aL[mi], bh[0], bh[1]);
                    }
                }
        }
        __syncthreads();
    }

    // epilogue
    const int g = lane >> 2, t = lane & 3;
#pragma unroll
    for (int mi = 0; mi < 2; mi++) {
        int row0 = bm + wm + mi * 16 + g;
#pragma unroll
        for (int nf = 0; nf < 4; nf++) {
            int col = bn + wn + nf * 8 + 2 * t;
            float b0 = bias ? bias[col] : 0.f;
            float b1 = bias ? bias[col + 1] : 0.f;
            float* c0 = C + (size_t)row0 * ldc + col;
            float* c1 = C + (size_t)(row0 + 8) * ldc + col;
            c0[0] = acc[mi][nf][0] + b0;  c0[1] = acc[mi][nf][1] + b1;
            c1[0] = acc[mi][nf][2] + b0;  c1[1] = acc[mi][nf][3] + b1;
        }
    }
}

// ---------------- conversion / split kernels ----------------
__device__ __forceinline__ void split2(float v, bf16& h, bf16& l) {
    h = __float2bfloat16(v);
    l = __float2bfloat16(v - __bfloat162float(h));
}

__global__ void split_mat(const float* __restrict__ src, int sld, int rows, int cols,
                          bf16* __restrict__ hi, bf16* __restrict__ lo, int dld) {
    int idx = blockIdx.x * blockDim.x + threadIdx.x;
    if (idx >= rows * dld) return;
    int r = idx / dld, c = idx - r * dld;
    float v = (c < cols) ? src[(size_t)r * sld + c] : 0.f;
    bf16 h = __float2bfloat16(v);
    hi[idx] = h;
    if (lo) lo[idx] = __float2bfloat16(v - __bfloat162float(h));
}

// ---------------- embeddings (write padded bf16 splits) ----------------
__global__ void embed_enc(const int* __restrict__ inputs, const float* __restrict__ Eenc) {
    int idx = blockIdx.x * blockDim.x + threadIdx.x;
    if (idx >= ENC_ROWS * KPAD) return;
    int row = idx >> 7, e = idx & (KPAD - 1);
    float v = (e < Esz) ? Eenc[(size_t)inputs[row] * Esz + e] : 0.f;
    split2(v, g_embE_h[idx], g_embE_l[idx]);
}

__global__ void embed_dec(const int* __restrict__ targets, const float* __restrict__ Edec) {
    int idx = blockIdx.x * blockDim.x + threadIdx.x;
    if (idx >= DEC_ROWS * KPAD) return;
    int row = idx >> 7, e = idx & (KPAD - 1);
    int b = row / TD, t = row - b * TD;
    int tok = (t == 0) ? 1 : targets[b * Tsz + t];   // [START, targets[:,1:T-1]]
    float v = (e < Esz) ? Edec[(size_t)tok * Esz + e] : 0.f;
    split2(v, g_embD_h[idx], g_embD_l[idx]);
}

// ---------------- hidden init ----------------
__global__ void init_h_enc(const float* __restrict__ h0) {
    int idx = blockIdx.x * blockDim.x + threadIdx.x;
    if (idx >= Bsz * Hsz) return;
    float v = h0[idx];
    g_h[idx] = v;
    split2(v, g_h_h[idx], g_h_l[idx]);
}
__global__ void init_h_dec() {
    int idx = blockIdx.x * blockDim.x + threadIdx.x;
    if (idx >= Bsz * Hsz) return;
    float v = g_context[idx];
    g_h[idx] = v;
    split2(v, g_h_h[idx], g_h_l[idx]);
}

// ---------------- GRU gate kernels ----------------
__device__ __forceinline__ float sigmoidf(float x) { return 1.f / (1.f + expf(-x)); }

__global__ void enc_gate(const int* __restrict__ lengths, int s) {
    int idx = blockIdx.x * blockDim.x + threadIdx.x;
    if (idx >= Bsz * Hsz) return;
    int b = idx >> 10, j = idx & (Hsz - 1);
    const float* gi = g_gi_e + (size_t)(b * Ssz + s) * TH3;
    const float* gh = g_gh + (size_t)b * TH3;
    float r = sigmoidf(gi[j] + gh[j]);
    float z = sigmoidf(gi[Hsz + j] + gh[Hsz + j]);
    float n = tanhf(gi[2 * Hsz + j] + r * gh[2 * Hsz + j]);
    float hnew = (1.f - z) * n + z * g_h[idx];
    g_h[idx] = hnew;
    split2(hnew, g_h_h[idx], g_h_l[idx]);
    if (lengths[b] - 1 == s) {
        g_context[idx] = hnew;
        split2(hnew, g_ctx_h[idx], g_ctx_l[idx]);
    }
}

__global__ void dec_gate(int t) {
    int idx = blockIdx.x * blockDim.x + threadIdx.x;
    if (idx >= Bsz * Hsz) return;
    int b = idx >> 10, j = idx & (Hsz - 1);
    const float* gi = g_gi_d + (size_t)(b * TD + t) * TH3;
    const float* gc = g_gctx + (size_t)b * TH3;
    const float* gh = g_gh + (size_t)b * TH3;
    float r = sigmoidf(gi[j] + gc[j] + gh[j]);
    float z = sigmoidf(gi[Hsz + j] + gc[Hsz + j] + gh[Hsz + j]);
    float n = tanhf(gi[2 * Hsz + j] + gc[2 * Hsz + j] + r * gh[2 * Hsz + j]);
    float hnew = (1.f - z) * n + z * g_h[idx];
    g_h[idx] = hnew;
    split2(hnew, g_h_h[idx], g_h_l[idx]);
    g_hall_h[(size_t)(t * Bsz + b) * Hsz + j] = __float2bfloat16(hnew);
}

// ---------------- cross entropy over logits rows ----------------
__global__ void ce_kernel(const int* __restrict__ targets) {
    int r = blockIdx.x;                   // r = t*B + b
    int t = r / Bsz, b = r - t * Bsz;
    const float* l = g_logits + (size_t)r * Vsz;
    __shared__ float sdata[256];
    int tid = threadIdx.x;
    float m = -FLT_MAX;
    for (int v = tid; v < Vsz; v += 256) m = fmaxf(m, l[v]);
    sdata[tid] = m; __syncthreads();
    for (int o = 128; o > 0; o >>= 1) {
        if (tid < o) sdata[tid] = fmaxf(sdata[tid], sdata[tid + o]);
        __syncthreads();
    }
    m = sdata[0]; __syncthreads();
    float s = 0.f;
    for (int v = tid; v < Vsz; v += 256) s += expf(l[v] - m);
    sdata[tid] = s; __syncthreads();
    for (int o = 128; o > 0; o >>= 1) {
        if (tid < o) sdata[tid] += sdata[tid + o];
        __syncthreads();
    }
    if (tid == 0) {
        int y = targets[b * Tsz + t + 1];
        g_ce[r] = m + logf(sdata[0]) - l[y];
        g_msk[r] = (y >= 1) ? 1.f : 0.f;
    }
}

__global__ void final_loss_kernel(float* __restrict__ out) {
    __shared__ float s1[256], s2[256];
    __shared__ float total;
    int tid = threadIdx.x;   // 256 == Bsz
    if (tid == 0) total = 0.f;
    __syncthreads();
    for (int t = 0; t < TD; t++) {
        s1[tid] = g_ce[t * Bsz + tid];
        s2[tid] = g_msk[t * Bsz + tid];
        __syncthreads();
        for (int o = 128; o > 0; o >>= 1) {
            if (tid < o) { s1[tid] += s1[tid + o]; s2[tid] += s2[tid + o]; }
            __syncthreads();
        }
        if (tid == 0) total += (s1[0] / Bsz) * (s2[0] / Bsz);
        __syncthreads();
    }
    if (tid == 0) out[0] = total / Tsz;
}

// ---------------- launch ----------------
extern "C" void kernel_launch(void* const* d_in, const int* in_sizes, int n_in,
                              void* d_out, int out_size) {
    const int*   inputs  = (const int*)  d_in[0];
    const int*   targets = (const int*)  d_in[1];
    const int*   lengths = (const int*)  d_in[2];
    const float* h0      = (const float*)d_in[3];
    const float* Eenc    = (const float*)d_in[4];
    const float* Edec    = (const float*)d_in[5];
    const float* Wih_e   = (const float*)d_in[6];   // [3H, E]
    const float* Whh_e   = (const float*)d_in[7];   // [3H, H]
    const float* bih_e   = (const float*)d_in[8];
    const float* bhh_e   = (const float*)d_in[9];
    const float* Wih_d   = (const float*)d_in[10];  // [3H, E+H]
    const float* Whh_d   = (const float*)d_in[11];  // [3H, H]
    const float* bih_d   = (const float*)d_in[12];
    const float* bhh_d   = (const float*)d_in[13];
    const float* Wfc     = (const float*)d_in[14];  // [V, H]
    const float* bfc     = (const float*)d_in[15];
    float* out = (float*)d_out;

    // device pointers to scratch
    bf16 *p_Wihe_h, *p_Wihe_l, *p_Wihdt_h, *p_Wihdt_l, *p_Wihdc_h, *p_Wihdc_l;
    bf16 *p_Whhe_h, *p_Whhe_l, *p_Whhd_h, *p_Whhd_l, *p_Wfc_h;
    bf16 *p_embE_h, *p_embE_l, *p_embD_h, *p_embD_l;
    bf16 *p_h_h, *p_h_l, *p_ctx_h, *p_ctx_l, *p_hall_h;
    float *p_gi_e, *p_gi_d, *p_gh, *p_gctx, *p_logits;
    cudaGetSymbolAddress((void**)&p_Wihe_h, g_Wihe_h);   cudaGetSymbolAddress((void**)&p_Wihe_l, g_Wihe_l);
    cudaGetSymbolAddress((void**)&p_Wihdt_h, g_Wihdt_h); cudaGetSymbolAddress((void**)&p_Wihdt_l, g_Wihdt_l);
    cudaGetSymbolAddress((void**)&p_Wihdc_h, g_Wihdc_h); cudaGetSymbolAddress((void**)&p_Wihdc_l, g_Wihdc_l);
    cudaGetSymbolAddress((void**)&p_Whhe_h, g_Whhe_h);   cudaGetSymbolAddress((void**)&p_Whhe_l, g_Whhe_l);
    cudaGetSymbolAddress((void**)&p_Whhd_h, g_Whhd_h);   cudaGetSymbolAddress((void**)&p_Whhd_l, g_Whhd_l);
    cudaGetSymbolAddress((void**)&p_Wfc_h, g_Wfc_h);
    cudaGetSymbolAddress((void**)&p_embE_h, g_embE_h);   cudaGetSymbolAddress((void**)&p_embE_l, g_embE_l);
    cudaGetSymbolAddress((void**)&p_embD_h, g_embD_h);   cudaGetSymbolAddress((void**)&p_embD_l, g_embD_l);
    cudaGetSymbolAddress((void**)&p_h_h, g_h_h);         cudaGetSymbolAddress((void**)&p_h_l, g_h_l);
    cudaGetSymbolAddress((void**)&p_ctx_h, g_ctx_h);     cudaGetSymbolAddress((void**)&p_ctx_l, g_ctx_l);
    cudaGetSymbolAddress((void**)&p_hall_h, g_hall_h);
    cudaGetSymbolAddress((void**)&p_gi_e, g_gi_e);
    cudaGetSymbolAddress((void**)&p_gi_d, g_gi_d);
    cudaGetSymbolAddress((void**)&p_gh, g_gh);
    cudaGetSymbolAddress((void**)&p_gctx, g_gctx);
    cudaGetSymbolAddress((void**)&p_logits, g_logits);

    const int EW = Bsz * Hsz;
    dim3 thr(256);
    auto blks = [](long n) { return (unsigned)((n + 255) / 256); };

    // --- weight splits ---
    split_mat<<<blks((long)TH3 * KPAD), thr>>>(Wih_e, Esz, TH3, Esz, p_Wihe_h, p_Wihe_l, KPAD);
    split_mat<<<blks((long)TH3 * KPAD), thr>>>(Wih_d, EH, TH3, Esz, p_Wihdt_h, p_Wihdt_l, KPAD);
    split_mat<<<blks((long)TH3 * Hsz), thr>>>(Wih_d + Esz, EH, TH3, Hsz, p_Wihdc_h, p_Wihdc_l, Hsz);
    split_mat<<<blks((long)TH3 * Hsz), thr>>>(Whh_e, Hsz, TH3, Hsz, p_Whhe_h, p_Whhe_l, Hsz);
    split_mat<<<blks((long)TH3 * Hsz), thr>>>(Whh_d, Hsz, TH3, Hsz, p_Whhd_h, p_Whhd_l, Hsz);
    split_mat<<<blks((long)Vsz * Hsz), thr>>>(Wfc, Hsz, Vsz, Hsz, p_Wfc_h, nullptr, Hsz);

    // --- encoder input gates (batched over all B*S rows) ---
    embed_enc<<<blks((long)ENC_ROWS * KPAD), thr>>>(inputs, Eenc);
    mma_gemm<3><<<dim3(TH3 / 64, ENC_ROWS / 64), 128>>>(
        p_embE_h, p_embE_l, KPAD, p_Wihe_h, p_Wihe_l, KPAD,
        bih_e, p_gi_e, TH3, ENC_ROWS, TH3, KPAD);

    // --- encoder recurrence ---
    init_h_enc<<<blks(EW), thr>>>(h0);
    for (int s = 0; s < Ssz; s++) {
        mma_gemm<3><<<dim3(TH3 / 64, Bsz / 64), 128>>>(
            p_h_h, p_h_l, Hsz, p_Whhe_h, p_Whhe_l, Hsz,
            bhh_e, p_gh, TH3, Bsz, TH3, Hsz);
        enc_gate<<<blks(EW), thr>>>(lengths, s);
    }

    // --- decoder input gates: ctx part (step-invariant) + token part ---
    init_h_dec<<<blks(EW), thr>>>();
    embed_dec<<<blks((long)DEC_ROWS * KPAD), thr>>>(targets, Edec);
    mma_gemm<3><<<dim3(TH3 / 64, Bsz / 64), 128>>>(
        p_ctx_h, p_ctx_l, Hsz, p_Wihdc_h, p_Wihdc_l, Hsz,
        bih_d, p_gctx, TH3, Bsz, TH3, Hsz);
    mma_gemm<3><<<dim3(TH3 / 64, DEC_ROWS / 64), 128>>>(
        p_embD_h, p_embD_l, KPAD, p_Wihdt_h, p_Wihdt_l, KPAD,
        nullptr, p_gi_d, TH3, DEC_ROWS, TH3, KPAD);

    // --- decoder recurrence ---
    for (int t = 0; t < TD; t++) {
        mma_gemm<3><<<dim3(TH3 / 64, Bsz / 64), 128>>>(
            p_h_h, p_h_l, Hsz, p_Whhd_h, p_Whhd_l, Hsz,
            bhh_d, p_gh, TH3, Bsz, TH3, Hsz);
        dec_gate<<<blks(EW), thr>>>(t);
    }

    // --- batched FC (plain bf16) + CE + loss ---
    mma_gemm<1><<<dim3(Vsz / 64, DEC_ROWS / 64), 128>>>(
        p_hall_h, nullptr, Hsz, p_Wfc_h, nullptr, Hsz,
        bfc, p_logits, Vsz, DEC_ROWS, Vsz, Hsz);
    ce_kernel<<<DEC_ROWS, thr>>>(targets);
    final_loss_kernel<<<1, thr>>>(out);
}